// round 15
// baseline (speedup 1.0000x reference)
#include <cuda_runtime.h>
#include <cuda_fp16.h>
#include <math.h>

#define NN 50000
#define NE 800000
#define ETOT 850000      // NE + NN self loops
#define FIN 128
#define D1 128           // NH*HID
#define NH 4
#define HID 32
#define NC 40
#define CSRB 296         // CSR blocks inside fused kernel (wave-1 co-resident with gemm1)
#define G1B 782          // gemm1 tile blocks

// ---------------- scratch (device globals) ----------------
__device__ __align__(16) __half2 g_h1h[NN * 64];     // x@W1 in fp16 (gather stream)
__device__ __align__(16) float g_esrc1[NN * 4];
__device__ __align__(16) float g_edst1[NN * 4];
__device__ __align__(16) __half g_agg1h[NN * D1];    // layer1 out in fp16 (GEMM2 A)
__device__ __align__(16) __half g_h2h[NN * NC];      // h@W2 in fp16 (gather stream)
__device__ float g_esrc2[NN];
__device__ float g_edst2[NN];
// global max of e_src; reset protocol:
//   g_gmax1 reset by gat2 (end of pipeline); g_gmax2 reset by fused1 (start)
__device__ float g_gmax1[NH] = {-1e30f, -1e30f, -1e30f, -1e30f};
__device__ float g_gmax2 = -1e30f;

// CSR scratch. g_cnt and g_bar zeroed by gat2 at end of each invocation
// (and zero-initialized at load).
__device__ int g_cnt[NN];
__device__ int g_bsum[CSRB];
__device__ int g_rowptr[NN + 1];
__device__ int g_cursor[NN];
__device__ __align__(16) int g_csrc[ETOT];
__device__ int g_bar[3];

// branch-free leaky-relu: slope 0.2 < 1 so max(v, 0.2v) == lrelu(v)
__device__ __forceinline__ float lrelu(float v) { return fmaxf(v, 0.2f * v); }

__device__ __forceinline__ void atomicMaxF(float* addr, float v) {
    int b = __float_as_int(v);
    if (b >= 0) atomicMax((int*)addr, b);
    else        atomicMin((unsigned int*)addr, (unsigned int)b);
}
__device__ __forceinline__ void atomicMaxFShared(int* addr, float v) {
    int b = __float_as_int(v);
    if (b >= 0) atomicMax(addr, b);
    else        atomicMin((unsigned int*)addr, (unsigned int)b);
}

// m16n8k16 fp16 MMA, row-major A, col-major B, fp32 accumulate
__device__ __forceinline__ void mma_f16(float* c, const unsigned* a, unsigned b0, unsigned b1) {
    asm volatile(
        "mma.sync.aligned.m16n8k16.row.col.f32.f16.f16.f32 "
        "{%0,%1,%2,%3}, {%4,%5,%6,%7}, {%8,%9}, {%0,%1,%2,%3};"
        : "+f"(c[0]), "+f"(c[1]), "+f"(c[2]), "+f"(c[3])
        : "r"(a[0]), "r"(a[1]), "r"(a[2]), "r"(a[3]), "r"(b0), "r"(b1));
}

// grid barrier among the CSRB csr blocks of the fused kernel
__device__ __forceinline__ void gridbar(int idx) {
    __syncthreads();
    if (threadIdx.x == 0) {
        __threadfence();
        atomicAdd(&g_bar[idx], 1);
        while (((volatile int*)g_bar)[idx] < CSRB) __nanosleep(64);
        __threadfence();
    }
    __syncthreads();
}

// ---------------- fused kernel: CSR build (blocks 0..CSRB-1) || GEMM1 (rest) ----------------
// dyn smem: Ah[64][136] half + Wth[128][136] half = 52224 B (gemm1); csr uses a slice
#define G1_SMEM ((64 * 136 + 128 * 136) * 2)
__global__ void __launch_bounds__(256, 4) fused1_kernel(
        const int* __restrict__ src, const int* __restrict__ dst,
        const float* __restrict__ A, const float* __restrict__ W,
        const float* __restrict__ asrc, const float* __restrict__ adst) {
    extern __shared__ char smraw[];
    int tid = threadIdx.x;

    if (blockIdx.x < CSRB) {
        // ================= CSR build =================
        int* s = (int*)smraw;            // [256]
        __shared__ int wsum[8];
        int gtid = blockIdx.x * 256 + tid;
        if (blockIdx.x == 0 && tid == 0) g_gmax2 = -1e30f;

        // phase 1: histogram of dst
        for (int e = gtid; e < NE; e += CSRB * 256)
            atomicAdd(&g_cnt[__ldg(dst + e)], 1);
        gridbar(0);

        // phase 2: block-local inclusive scan of (cnt+1), block totals
        int i = gtid;
        int val = (i < NN) ? (__ldcg(&g_cnt[i]) + 1) : 0;
        s[tid] = val;
        __syncthreads();
        #pragma unroll
        for (int off = 1; off < 256; off <<= 1) {
            int v = (tid >= off) ? s[tid - off] : 0;
            __syncthreads();
            s[tid] += v;
            __syncthreads();
        }
        int incl = s[tid];
        if (tid == 255) g_bsum[blockIdx.x] = incl;
        gridbar(1);

        // phase 3: cross-block prefix; emit rowptr/cursor/self-loop
        {
            int acc = 0;
            for (int k = tid; k < blockIdx.x; k += 256) acc += __ldcg(&g_bsum[k]);
            int lane = tid & 31;
            #pragma unroll
            for (int o = 16; o >= 1; o >>= 1) acc += __shfl_xor_sync(0xffffffffu, acc, o);
            if (lane == 0) wsum[tid >> 5] = acc;
            __syncthreads();
            int prefix = wsum[0] + wsum[1] + wsum[2] + wsum[3]
                       + wsum[4] + wsum[5] + wsum[6] + wsum[7];
            if (i < NN) {
                int rp = prefix + incl - val;
                g_rowptr[i] = rp;
                g_csrc[rp] = i;          // self loop in slot 0
                g_cursor[i] = rp + 1;
            }
            if (i == NN) g_rowptr[NN] = ETOT;
        }
        gridbar(2);

        // phase 4: place edges
        for (int e = gtid; e < NE; e += CSRB * 256) {
            int dd = __ldg(dst + e);
            int ss = __ldg(src + e);
            int pos = atomicAdd(&g_cursor[dd], 1);
            g_csrc[pos] = ss;
        }
        return;
    }

    // ================= GEMM1 (fp16 mma) + logits + gmax =================
    __half* Ah  = (__half*)smraw;             // [64][136]
    __half* Wth = (__half*)smraw + 64 * 136;  // [128 n][136 k]
    __shared__ int smax[4];
    int brow = (blockIdx.x - CSRB) * 64;
    if (tid < 4) smax[tid] = 0xFF800000;   // -inf bits
    // stage A tile as fp16
    #pragma unroll
    for (int p = 0; p < 8; p++) {
        int idx = tid + p * 256;
        int m = idx >> 5;
        int k4 = (idx & 31) * 4;
        int gr = brow + m;
        float4 v = (gr < NN) ? *(const float4*)(A + (size_t)gr * FIN + k4)
                             : make_float4(0.f, 0.f, 0.f, 0.f);
        __half2 h0 = __floats2half2_rn(v.x, v.y);
        __half2 h1 = __floats2half2_rn(v.z, v.w);
        *(uint2*)(Ah + m * 136 + k4) = make_uint2(*(unsigned*)&h0, *(unsigned*)&h1);
    }
    // stage W transposed as fp16: Wth[n][k]
    #pragma unroll
    for (int p = 0; p < 16; p++) {
        int idx = tid + p * 256;        // 4096 float4 groups
        int k = idx >> 5;
        int n4 = (idx & 31) * 4;
        float4 w = __ldg((const float4*)(W + k * D1 + n4));
        Wth[(n4 + 0) * 136 + k] = __float2half(w.x);
        Wth[(n4 + 1) * 136 + k] = __float2half(w.y);
        Wth[(n4 + 2) * 136 + k] = __float2half(w.z);
        Wth[(n4 + 3) * 136 + k] = __float2half(w.w);
    }
    __syncthreads();
    int wid = tid >> 5, lane = tid & 31;
    int wm = wid & 1, wn = wid >> 1;        // 2 M-groups x 4 N-groups of 32
    int g = lane >> 2, t = lane & 3;
    float c[2][4][4];
    #pragma unroll
    for (int mi = 0; mi < 2; mi++)
        #pragma unroll
        for (int ni = 0; ni < 4; ni++)
            #pragma unroll
            for (int q = 0; q < 4; q++) c[mi][ni][q] = 0.f;
    #pragma unroll
    for (int k0 = 0; k0 < 128; k0 += 16) {
        unsigned a[2][4];
        #pragma unroll
        for (int mi = 0; mi < 2; mi++) {
            const __half* ap = Ah + (wm * 32 + mi * 16 + g) * 136 + k0 + 2 * t;
            a[mi][0] = *(const unsigned*)(ap);
            a[mi][1] = *(const unsigned*)(ap + 8 * 136);
            a[mi][2] = *(const unsigned*)(ap + 8);
            a[mi][3] = *(const unsigned*)(ap + 8 * 136 + 8);
        }
        unsigned b[4][2];
        #pragma unroll
        for (int ni = 0; ni < 4; ni++) {
            const __half* bp = Wth + (wn * 32 + ni * 8 + g) * 136 + k0 + 2 * t;
            b[ni][0] = *(const unsigned*)(bp);
            b[ni][1] = *(const unsigned*)(bp + 8);
        }
        #pragma unroll
        for (int mi = 0; mi < 2; mi++)
            #pragma unroll
            for (int ni = 0; ni < 4; ni++)
                mma_f16(c[mi][ni], a[mi], b[ni][0], b[ni][1]);
    }
    // stage C (fp32) into smem [64][132]
    __syncthreads();
    float* Sh = (float*)smraw;
    #pragma unroll
    for (int mi = 0; mi < 2; mi++)
        #pragma unroll
        for (int ni = 0; ni < 4; ni++) {
            int r = wm * 32 + mi * 16 + g;
            int col = wn * 32 + ni * 8 + 2 * t;
            Sh[r * 132 + col]           = c[mi][ni][0];
            Sh[r * 132 + col + 1]       = c[mi][ni][1];
            Sh[(r + 8) * 132 + col]     = c[mi][ni][2];
            Sh[(r + 8) * 132 + col + 1] = c[mi][ni][3];
        }
    __syncthreads();
    // fp16 h1 write
    #pragma unroll
    for (int p = 0; p < 8; p++) {
        int task = tid + p * 256;       // 2048 tasks: 64 rows x 32 col-groups(4)
        int row = task >> 5;
        int c4 = (task & 31) * 4;
        int grow = brow + row;
        if (grow < NN) {
            float4 f = *(const float4*)&Sh[row * 132 + c4];
            __half2 h0 = __floats2half2_rn(f.x, f.y);
            __half2 h1 = __floats2half2_rn(f.z, f.w);
            uint2 u = make_uint2(*(unsigned*)&h0, *(unsigned*)&h1);
            *(uint2*)(g_h1h + (size_t)grow * 64 + (task & 31) * 2) = u;
        }
    }
    // attention logits + gmax
    int h = lane >> 3;
    int off = (lane & 7) * 4;
    float4 a4 = *(const float4*)(asrc + h * HID + off);
    float4 d4 = *(const float4*)(adst + h * HID + off);
    #pragma unroll
    for (int rr = 0; rr < 8; rr++) {
        int row = wid * 8 + rr;
        int grow = brow + row;
        float4 hv = *(const float4*)&Sh[row * 132 + lane * 4];
        float ps = hv.x * a4.x + hv.y * a4.y + hv.z * a4.z + hv.w * a4.w;
        float pd = hv.x * d4.x + hv.y * d4.y + hv.z * d4.z + hv.w * d4.w;
        #pragma unroll
        for (int o = 4; o >= 1; o >>= 1) {
            ps += __shfl_xor_sync(0xffffffffu, ps, o);
            pd += __shfl_xor_sync(0xffffffffu, pd, o);
        }
        if ((lane & 7) == 0 && grow < NN) {
            g_esrc1[grow * 4 + h] = ps;
            g_edst1[grow * 4 + h] = pd;
            atomicMaxFShared(&smax[h], ps);
        }
    }
    __syncthreads();
    if (tid < 4) atomicMaxF(&g_gmax1[tid], __int_as_float(smax[tid]));
}

// ---------------- GAT layer 1: cooperative-weight shifted softmax + fp16 gather ----------------
__global__ void gat1_kernel(const float* __restrict__ bias) {
    int warp = (blockIdx.x * blockDim.x + threadIdx.x) >> 5;
    int lane = threadIdx.x & 31;
    if (warp >= NN) return;
    int d = warp;
    int base = g_rowptr[d];
    int end  = g_rowptr[d + 1];
    int h = lane >> 3;
    float4 ed4 = *(const float4*)(g_edst1 + d * 4);
    float S0 = lrelu(g_gmax1[0] + ed4.x);
    float S1 = lrelu(g_gmax1[1] + ed4.y);
    float S2 = lrelu(g_gmax1[2] + ed4.z);
    float S3 = lrelu(g_gmax1[3] + ed4.w);
    // own-head constants (scalar-edge path)
    float ed_h = (h == 0) ? ed4.x : (h == 1) ? ed4.y : (h == 2) ? ed4.z : ed4.w;
    float S_h  = (h == 0) ? S0 : (h == 1) ? S1 : (h == 2) ? S2 : S3;
    // vector-body: lane computes w for (edge eSel, head hSel); lanes 16..31 duplicate 0..15
    int eSel = (lane >> 2) & 3;
    int hSel = lane & 3;
    float edv = (hSel == 0) ? ed4.x : (hSel == 1) ? ed4.y : (hSel == 2) ? ed4.z : ed4.w;
    float Sv  = (hSel == 0) ? S0 : (hSel == 1) ? S1 : (hSel == 2) ? S2 : S3;

    float sum = 0.f;
    float4 acc = make_float4(0.f, 0.f, 0.f, 0.f);
    int j = base;
    int lim = min(end, (base + 3) & ~3);
    for (; j < lim; j++) {
        int s0 = g_csrc[j];
        float w0 = __expf(lrelu(g_esrc1[s0 * 4 + h] + ed_h) - S_h);
        sum += w0;
        uint2 r0 = *(const uint2*)(g_h1h + (size_t)s0 * 64 + lane * 2);
        float2 p;
        p = __half22float2(*(__half2*)&r0.x); acc.x += w0 * p.x; acc.y += w0 * p.y;
        p = __half22float2(*(__half2*)&r0.y); acc.z += w0 * p.x; acc.w += w0 * p.y;
    }
    for (; j + 3 < end; j += 4) {
        int4 s4 = *(const int4*)(g_csrc + j);
        int ss = (eSel == 0) ? s4.x : (eSel == 1) ? s4.y : (eSel == 2) ? s4.z : s4.w;
        float w = __expf(lrelu(g_esrc1[ss * 4 + hSel] + edv) - Sv);
        // lane needs w for each edge e at its own head h: source lane = e*4 + h
        float w0 = __shfl_sync(0xffffffffu, w, h);
        float w1 = __shfl_sync(0xffffffffu, w, 4 + h);
        float w2 = __shfl_sync(0xffffffffu, w, 8 + h);
        float w3 = __shfl_sync(0xffffffffu, w, 12 + h);
        sum += (w0 + w1) + (w2 + w3);
        uint2 r0 = *(const uint2*)(g_h1h + (size_t)s4.x * 64 + lane * 2);
        uint2 r1 = *(const uint2*)(g_h1h + (size_t)s4.y * 64 + lane * 2);
        uint2 r2 = *(const uint2*)(g_h1h + (size_t)s4.z * 64 + lane * 2);
        uint2 r3 = *(const uint2*)(g_h1h + (size_t)s4.w * 64 + lane * 2);
        float2 p;
        p = __half22float2(*(__half2*)&r0.x); acc.x += w0 * p.x; acc.y += w0 * p.y;
        p = __half22float2(*(__half2*)&r0.y); acc.z += w0 * p.x; acc.w += w0 * p.y;
        p = __half22float2(*(__half2*)&r1.x); acc.x += w1 * p.x; acc.y += w1 * p.y;
        p = __half22float2(*(__half2*)&r1.y); acc.z += w1 * p.x; acc.w += w1 * p.y;
        p = __half22float2(*(__half2*)&r2.x); acc.x += w2 * p.x; acc.y += w2 * p.y;
        p = __half22float2(*(__half2*)&r2.y); acc.z += w2 * p.x; acc.w += w2 * p.y;
        p = __half22float2(*(__half2*)&r3.x); acc.x += w3 * p.x; acc.y += w3 * p.y;
        p = __half22float2(*(__half2*)&r3.y); acc.z += w3 * p.x; acc.w += w3 * p.y;
    }
    for (; j < end; j++) {
        int s0 = g_csrc[j];
        float w0 = __expf(lrelu(g_esrc1[s0 * 4 + h] + ed_h) - S_h);
        sum += w0;
        uint2 r0 = *(const uint2*)(g_h1h + (size_t)s0 * 64 + lane * 2);
        float2 p;
        p = __half22float2(*(__half2*)&r0.x); acc.x += w0 * p.x; acc.y += w0 * p.y;
        p = __half22float2(*(__half2*)&r0.y); acc.z += w0 * p.x; acc.w += w0 * p.y;
    }
    float inv = 1.0f / (sum + 1e-16f);
    float4 b = *(const float4*)(bias + lane * 4);
    float4 v;
    v.x = acc.x * inv + b.x;
    v.y = acc.y * inv + b.y;
    v.z = acc.z * inv + b.z;
    v.w = acc.w * inv + b.w;
    v.x = v.x > 0.f ? v.x : (__expf(v.x) - 1.f);
    v.y = v.y > 0.f ? v.y : (__expf(v.y) - 1.f);
    v.z = v.z > 0.f ? v.z : (__expf(v.z) - 1.f);
    v.w = v.w > 0.f ? v.w : (__expf(v.w) - 1.f);
    // store fp16 directly (GEMM2 consumes fp16)
    __half2 o0 = __floats2half2_rn(v.x, v.y);
    __half2 o1 = __floats2half2_rn(v.z, v.w);
    *(uint2*)(g_agg1h + (size_t)d * D1 + lane * 4) = make_uint2(*(unsigned*)&o0, *(unsigned*)&o1);
}

// ---------------- GEMM2 (fp16 mma m16n8k16) + logits + gmax ----------------
// dyn smem: Ah[128][136] + Wth[40][136] halves = 45696 B
#define G2_SMEM ((128 * 136 + 40 * 136) * 2)
__global__ void __launch_bounds__(256, 3) gemm2_kernel(
        const float* __restrict__ W,
        const float* __restrict__ asrc, const float* __restrict__ adst) {
    extern __shared__ __half sm2h[];
    __half* Ah  = sm2h;                // [128][136]
    __half* Wth = sm2h + 128 * 136;    // [40 n][136 k]
    __shared__ int smax2;
    int tid = threadIdx.x;
    int brow = blockIdx.x * 128;
    if (tid == 0) smax2 = 0xFF800000;
    // stage A tile (already fp16): pure uint4 copies, 8 per thread
    #pragma unroll
    for (int p = 0; p < 8; p++) {
        int idx = tid + p * 256;        // 2048 uint4 = 128 rows x 16 groups
        int m = idx >> 4;
        int h8 = (idx & 15) * 8;
        int gr = brow + m;
        uint4 v = (gr < NN) ? *(const uint4*)(g_agg1h + (size_t)gr * D1 + h8)
                            : make_uint4(0u, 0u, 0u, 0u);
        *(uint4*)(Ah + m * 136 + h8) = v;
    }
    // stage W2 transposed as fp16: Wth[n][k], W2 is [128][40]
    #pragma unroll
    for (int p = 0; p < 5; p++) {
        int idx = tid + p * 256;        // 1280 float4 groups
        int k = idx / 10;
        int n4 = (idx % 10) * 4;
        float4 w = __ldg((const float4*)(W + k * NC + n4));
        Wth[(n4 + 0) * 136 + k] = __float2half(w.x);
        Wth[(n4 + 1) * 136 + k] = __float2half(w.y);
        Wth[(n4 + 2) * 136 + k] = __float2half(w.z);
        Wth[(n4 + 3) * 136 + k] = __float2half(w.w);
    }
    __syncthreads();
    int wid = tid >> 5, lane = tid & 31;
    int g = lane >> 2, t = lane & 3;
    float c[5][4];
    #pragma unroll
    for (int ni = 0; ni < 5; ni++)
        #pragma unroll
        for (int q = 0; q < 4; q++) c[ni][q] = 0.f;
    #pragma unroll
    for (int k0 = 0; k0 < 128; k0 += 16) {
        unsigned a[4];
        const __half* ap = Ah + (wid * 16 + g) * 136 + k0 + 2 * t;
        a[0] = *(const unsigned*)(ap);
        a[1] = *(const unsigned*)(ap + 8 * 136);
        a[2] = *(const unsigned*)(ap + 8);
        a[3] = *(const unsigned*)(ap + 8 * 136 + 8);
        #pragma unroll
        for (int ni = 0; ni < 5; ni++) {
            const __half* bp = Wth + (ni * 8 + g) * 136 + k0 + 2 * t;
            mma_f16(c[ni], a, *(const unsigned*)(bp), *(const unsigned*)(bp + 8));
        }
    }
    // stage C into smem [128][44]
    __syncthreads();
    float* Sh = (float*)sm2h;
    #pragma unroll
    for (int ni = 0; ni < 5; ni++) {
        int r = wid * 16 + g;
        int col = ni * 8 + 2 * t;
        Sh[r * 44 + col]           = c[ni][0];
        Sh[r * 44 + col + 1]       = c[ni][1];
        Sh[(r + 8) * 44 + col]     = c[ni][2];
        Sh[(r + 8) * 44 + col + 1] = c[ni][3];
    }
    __syncthreads();
    // fp16 h2 write: 2 threads per row, 20 cols each
    {
        int row = tid >> 1;
        int half = tid & 1;
        int grow = brow + row;
        if (grow < NN) {
            const float* sp = &Sh[row * 44 + half * 20];
            uint2* op = (uint2*)(g_h2h + (size_t)grow * NC + half * 20);
            #pragma unroll
            for (int i = 0; i < 5; i++) {
                __half2 h0 = __floats2half2_rn(sp[4 * i],     sp[4 * i + 1]);
                __half2 h1 = __floats2half2_rn(sp[4 * i + 2], sp[4 * i + 3]);
                op[i] = make_uint2(*(unsigned*)&h0, *(unsigned*)&h1);
            }
        }
    }
    // attention logits + gmax: each warp handles 16 rows
    float a_lo = __ldg(asrc + lane);
    float d_lo = __ldg(adst + lane);
    float a_hi = (lane < 8) ? __ldg(asrc + 32 + lane) : 0.f;
    float d_hi = (lane < 8) ? __ldg(adst + 32 + lane) : 0.f;
    #pragma unroll
    for (int rr = 0; rr < 16; rr++) {
        int row = wid * 16 + rr;
        int grow = brow + row;
        float v0 = Sh[row * 44 + lane];
        float v1 = (lane < 8) ? Sh[row * 44 + 32 + lane] : 0.f;
        float ps = v0 * a_lo + v1 * a_hi;
        float pd = v0 * d_lo + v1 * d_hi;
        #pragma unroll
        for (int o = 16; o >= 1; o >>= 1) {
            ps += __shfl_xor_sync(0xffffffffu, ps, o);
            pd += __shfl_xor_sync(0xffffffffu, pd, o);
        }
        if (lane == 0 && grow < NN) {
            g_esrc2[grow] = ps;
            g_edst2[grow] = pd;
            atomicMaxFShared(&smax2, ps);
        }
    }
    __syncthreads();
    if (tid == 0) atomicMaxF(&g_gmax2, __int_as_float(smax2));
}

// ---------------- GAT layer 2: cooperative-weight softmax + half2 gather + log_softmax/softmax ----------------
__global__ void gat2_kernel(const float* __restrict__ bias, float* __restrict__ out) {
    int warp = (blockIdx.x * blockDim.x + threadIdx.x) >> 5;
    int lane = threadIdx.x & 31;
    if (blockIdx.x == 0) {
        if (threadIdx.x < 4) g_gmax1[threadIdx.x] = -1e30f;          // reset for next invocation
        else if (threadIdx.x < 7) g_bar[threadIdx.x - 4] = 0;         // reset grid barriers
    }
    if (warp >= NN) return;
    int d = warp;
    if (lane == 0) g_cnt[d] = 0;   // reset histogram for next invocation
    int base = g_rowptr[d];
    int end  = g_rowptr[d + 1];
    float ed = g_edst2[d];
    float S = lrelu(g_gmax2 + ed);
    bool act = (lane < 20);        // lanes 0..19 own feature pairs (2l, 2l+1)
    int eSel = lane & 3;
    int bl = lane & ~3;

    float sum = 0.f;
    float2 acc = make_float2(0.f, 0.f);
    int j = base;
    int lim = min(end, (base + 3) & ~3);
    for (; j < lim; j++) {
        int s0 = g_csrc[j];
        float w0 = __expf(lrelu(g_esrc2[s0] + ed) - S);
        sum += w0;
        if (act) {
            unsigned u0 = *(const unsigned*)(g_h2h + (size_t)s0 * NC + 2 * lane);
            float2 p0 = __half22float2(*(__half2*)&u0);
            acc.x += w0 * p0.x; acc.y += w0 * p0.y;
        }
    }
    for (; j + 3 < end; j += 4) {
        int4 s4 = *(const int4*)(g_csrc + j);
        int ss = (eSel == 0) ? s4.x : (eSel == 1) ? s4.y : (eSel == 2) ? s4.z : s4.w;
        float w = __expf(lrelu(g_esrc2[ss] + ed) - S);
        float w0 = __shfl_sync(0xffffffffu, w, bl);
        float w1 = __shfl_sync(0xffffffffu, w, bl + 1);
        float w2 = __shfl_sync(0xffffffffu, w, bl + 2);
        float w3 = __shfl_sync(0xffffffffu, w, bl + 3);
        sum += (w0 + w1) + (w2 + w3);
        if (act) {
            unsigned u0 = *(const unsigned*)(g_h2h + (size_t)s4.x * NC + 2 * lane);
            unsigned u1 = *(const unsigned*)(g_h2h + (size_t)s4.y * NC + 2 * lane);
            unsigned u2 = *(const unsigned*)(g_h2h + (size_t)s4.z * NC + 2 * lane);
            unsigned u3 = *(const unsigned*)(g_h2h + (size_t)s4.w * NC + 2 * lane);
            float2 p0 = __half22float2(*(__half2*)&u0);
            float2 p1 = __half22float2(*(__half2*)&u1);
            float2 p2 = __half22float2(*(__half2*)&u2);
            float2 p3 = __half22float2(*(__half2*)&u3);
            acc.x += w0 * p0.x + w1 * p1.x;
            acc.y += w0 * p0.y + w1 * p1.y;
            acc.x += w2 * p2.x + w3 * p3.x;
            acc.y += w2 * p2.y + w3 * p3.y;
        }
    }
    for (; j < end; j++) {
        int s0 = g_csrc[j];
        float w0 = __expf(lrelu(g_esrc2[s0] + ed) - S);
        sum += w0;
        if (act) {
            unsigned u0 = *(const unsigned*)(g_h2h + (size_t)s0 * NC + 2 * lane);
            float2 p0 = __half22float2(*(__half2*)&u0);
            acc.x += w0 * p0.x; acc.y += w0 * p0.y;
        }
    }
    float inv = 1.0f / (sum + 1e-16f);
    float2 bb = act ? __ldg((const float2*)bias + lane) : make_float2(0.f, 0.f);
    float v0 = acc.x * inv + bb.x;   // class 2*lane
    float v1 = acc.y * inv + bb.y;   // class 2*lane+1
    float m = act ? fmaxf(v0, v1) : -INFINITY;
    #pragma unroll
    for (int o = 16; o >= 1; o >>= 1) m = fmaxf(m, __shfl_xor_sync(0xffffffffu, m, o));
    float e0 = act ? expf(v0 - m) : 0.f;
    float e1 = act ? expf(v1 - m) : 0.f;
    float sm = e0 + e1;
    #pragma unroll
    for (int o = 16; o >= 1; o >>= 1) sm += __shfl_xor_sync(0xffffffffu, sm, o);
    float ls = logf(sm);
    float invs = 1.0f / sm;
    if (act) {
        float* lo = out + (size_t)d * NC + 2 * lane;
        float* so = out + (size_t)NN * NC + (size_t)d * NC + 2 * lane;
        *(float2*)lo = make_float2(v0 - m - ls, v1 - m - ls);
        *(float2*)so = make_float2(e0 * invs, e1 * invs);
    }
}

// ---------------- launch ----------------
extern "C" void kernel_launch(void* const* d_in, const int* in_sizes, int n_in,
                              void* d_out, int out_size) {
    const float* x   = (const float*)d_in[0];
    const int*   ei  = (const int*)d_in[1];
    const float* W1  = (const float*)d_in[2];
    const float* as1 = (const float*)d_in[3];
    const float* ad1 = (const float*)d_in[4];
    const float* b1  = (const float*)d_in[5];
    const float* W2  = (const float*)d_in[6];
    const float* as2 = (const float*)d_in[7];
    const float* ad2 = (const float*)d_in[8];
    const float* b2  = (const float*)d_in[9];
    float* out = (float*)d_out;
    const int* src = ei;
    const int* dst = ei + NE;

    cudaFuncSetAttribute(fused1_kernel, cudaFuncAttributeMaxDynamicSharedMemorySize, G1_SMEM);
    cudaFuncSetAttribute(gemm2_kernel, cudaFuncAttributeMaxDynamicSharedMemorySize, G2_SMEM);

    fused1_kernel<<<CSRB + G1B, 256, G1_SMEM>>>(src, dst, x, W1, as1, ad1);
    gat1_kernel<<<6250, 256>>>(b1);
    gemm2_kernel<<<391, 256, G2_SMEM>>>(W2, as2, ad2);
    gat2_kernel<<<6250, 256>>>(b2, out);
}

// round 16
// speedup vs baseline: 1.1850x; 1.1850x over previous
#include <cuda_runtime.h>
#include <cuda_fp16.h>
#include <math.h>

#define NN 50000
#define NE 800000
#define ETOT 850000      // NE + NN self loops
#define FIN 128
#define D1 128           // NH*HID
#define NH 4
#define HID 32
#define NC 40
#define CSRB 296         // CSR blocks inside fused kernel (wave-1 co-resident with gemm1)
#define G1B 782          // gemm1 tile blocks

// ---------------- scratch (device globals) ----------------
__device__ __align__(16) __half2 g_h1h[NN * 64];     // x@W1 in fp16 (gather stream)
__device__ __align__(16) float g_esrc1[NN * 4];
__device__ __align__(16) float g_edst1[NN * 4];
__device__ __align__(16) __half g_agg1h[NN * D1];    // layer1 out in fp16 (GEMM2 A)
__device__ __align__(16) __half g_h2h[NN * NC];      // h@W2 in fp16 (gather stream)
__device__ float g_esrc2[NN];
__device__ float g_edst2[NN];
// pre-transposed fp16 weights (built once per invocation by prep_kernel)
__device__ __align__(16) __half g_w1t[128 * 128];    // [n][k]
__device__ __align__(16) __half g_w2t[40 * 128];     // [n][k]
// global max of e_src; reset protocol:
//   g_gmax1 reset by gat2 (end of pipeline); g_gmax2 reset by prep_kernel (start)
__device__ float g_gmax1[NH] = {-1e30f, -1e30f, -1e30f, -1e30f};
__device__ float g_gmax2 = -1e30f;

// CSR scratch. g_cnt and g_bar zeroed by gat2 at end of each invocation
// (and zero-initialized at load).
__device__ int g_cnt[NN];
__device__ int g_bsum[CSRB];
__device__ int g_rowptr[NN + 1];
__device__ int g_cursor[NN];
__device__ __align__(16) int g_csrc[ETOT];
__device__ int g_bar[3];

// branch-free leaky-relu: slope 0.2 < 1 so max(v, 0.2v) == lrelu(v)
__device__ __forceinline__ float lrelu(float v) { return fmaxf(v, 0.2f * v); }

__device__ __forceinline__ void atomicMaxF(float* addr, float v) {
    int b = __float_as_int(v);
    if (b >= 0) atomicMax((int*)addr, b);
    else        atomicMin((unsigned int*)addr, (unsigned int)b);
}
__device__ __forceinline__ void atomicMaxFShared(int* addr, float v) {
    int b = __float_as_int(v);
    if (b >= 0) atomicMax(addr, b);
    else        atomicMin((unsigned int*)addr, (unsigned int)b);
}

// m16n8k16 fp16 MMA, row-major A, col-major B, fp32 accumulate
__device__ __forceinline__ void mma_f16(float* c, const unsigned* a, unsigned b0, unsigned b1) {
    asm volatile(
        "mma.sync.aligned.m16n8k16.row.col.f32.f16.f16.f32 "
        "{%0,%1,%2,%3}, {%4,%5,%6,%7}, {%8,%9}, {%0,%1,%2,%3};"
        : "+f"(c[0]), "+f"(c[1]), "+f"(c[2]), "+f"(c[3])
        : "r"(a[0]), "r"(a[1]), "r"(a[2]), "r"(a[3]), "r"(b0), "r"(b1));
}

// grid barrier among the CSRB csr blocks of the fused kernel
__device__ __forceinline__ void gridbar(int idx) {
    __syncthreads();
    if (threadIdx.x == 0) {
        __threadfence();
        atomicAdd(&g_bar[idx], 1);
        while (((volatile int*)g_bar)[idx] < CSRB) __nanosleep(64);
        __threadfence();
    }
    __syncthreads();
}

// ---------------- prep: transpose weights to fp16 once ----------------
__global__ void prep_kernel(const float* __restrict__ W1, const float* __restrict__ W2) {
    int idx = blockIdx.x * 256 + threadIdx.x;
    if (idx == 0) g_gmax2 = -1e30f;
    if (idx < 128 * 128) {
        int n = idx >> 7, k = idx & 127;
        g_w1t[n * 128 + k] = __float2half(__ldg(W1 + k * D1 + n));
    } else if (idx < 128 * 128 + 40 * 128) {
        int r = idx - 128 * 128;
        int n = r >> 7, k = r & 127;
        g_w2t[n * 128 + k] = __float2half(__ldg(W2 + k * NC + n));
    }
}

// ---------------- fused kernel: CSR build (blocks 0..CSRB-1) || GEMM1 (rest) ----------------
// dyn smem: Ah[64][136] half + Wth[128][136] half = 52224 B (gemm1); csr uses a slice
#define G1_SMEM ((64 * 136 + 128 * 136) * 2)
__global__ void __launch_bounds__(256, 4) fused1_kernel(
        const int* __restrict__ src, const int* __restrict__ dst,
        const float* __restrict__ A,
        const float* __restrict__ asrc, const float* __restrict__ adst) {
    extern __shared__ char smraw[];
    int tid = threadIdx.x;

    if (blockIdx.x < CSRB) {
        // ================= CSR build =================
        int* s = (int*)smraw;            // [256]
        __shared__ int wsum[8];
        int gtid = blockIdx.x * 256 + tid;

        // phase 1: histogram of dst
        for (int e = gtid; e < NE; e += CSRB * 256)
            atomicAdd(&g_cnt[__ldg(dst + e)], 1);
        gridbar(0);

        // phase 2: block-local inclusive scan of (cnt+1), block totals
        int i = gtid;
        int val = (i < NN) ? (__ldcg(&g_cnt[i]) + 1) : 0;
        s[tid] = val;
        __syncthreads();
        #pragma unroll
        for (int off = 1; off < 256; off <<= 1) {
            int v = (tid >= off) ? s[tid - off] : 0;
            __syncthreads();
            s[tid] += v;
            __syncthreads();
        }
        int incl = s[tid];
        if (tid == 255) g_bsum[blockIdx.x] = incl;
        gridbar(1);

        // phase 3: cross-block prefix; emit rowptr/cursor/self-loop
        {
            int acc = 0;
            for (int k = tid; k < blockIdx.x; k += 256) acc += __ldcg(&g_bsum[k]);
            int lane = tid & 31;
            #pragma unroll
            for (int o = 16; o >= 1; o >>= 1) acc += __shfl_xor_sync(0xffffffffu, acc, o);
            if (lane == 0) wsum[tid >> 5] = acc;
            __syncthreads();
            int prefix = wsum[0] + wsum[1] + wsum[2] + wsum[3]
                       + wsum[4] + wsum[5] + wsum[6] + wsum[7];
            if (i < NN) {
                int rp = prefix + incl - val;
                g_rowptr[i] = rp;
                g_csrc[rp] = i;          // self loop in slot 0
                g_cursor[i] = rp + 1;
            }
            if (i == NN) g_rowptr[NN] = ETOT;
        }
        gridbar(2);

        // phase 4: place edges
        for (int e = gtid; e < NE; e += CSRB * 256) {
            int dd = __ldg(dst + e);
            int ss = __ldg(src + e);
            int pos = atomicAdd(&g_cursor[dd], 1);
            g_csrc[pos] = ss;
        }
        return;
    }

    // ================= GEMM1 (fp16 mma) + logits + gmax =================
    __half* Ah  = (__half*)smraw;             // [64][136]
    __half* Wth = (__half*)smraw + 64 * 136;  // [128 n][136 k]
    __shared__ int smax[4];
    int brow = (blockIdx.x - CSRB) * 64;
    if (tid < 4) smax[tid] = 0xFF800000;   // -inf bits
    // stage A tile as fp16
    #pragma unroll
    for (int p = 0; p < 8; p++) {
        int idx = tid + p * 256;
        int m = idx >> 5;
        int k4 = (idx & 31) * 4;
        int gr = brow + m;
        float4 v = (gr < NN) ? *(const float4*)(A + (size_t)gr * FIN + k4)
                             : make_float4(0.f, 0.f, 0.f, 0.f);
        __half2 h0 = __floats2half2_rn(v.x, v.y);
        __half2 h1 = __floats2half2_rn(v.z, v.w);
        *(uint2*)(Ah + m * 136 + k4) = make_uint2(*(unsigned*)&h0, *(unsigned*)&h1);
    }
    // stage W from pre-transposed fp16: pure uint4 copies (2048 tasks)
    #pragma unroll
    for (int p = 0; p < 8; p++) {
        int idx = tid + p * 256;
        int n = idx >> 4;
        int gq = (idx & 15) * 8;
        *(uint4*)(Wth + n * 136 + gq) = *(const uint4*)(g_w1t + n * 128 + gq);
    }
    __syncthreads();
    int wid = tid >> 5, lane = tid & 31;
    int wm = wid & 1, wn = wid >> 1;        // 2 M-groups x 4 N-groups of 32
    int g = lane >> 2, t = lane & 3;
    float c[2][4][4];
    #pragma unroll
    for (int mi = 0; mi < 2; mi++)
        #pragma unroll
        for (int ni = 0; ni < 4; ni++)
            #pragma unroll
            for (int q = 0; q < 4; q++) c[mi][ni][q] = 0.f;
    #pragma unroll
    for (int k0 = 0; k0 < 128; k0 += 16) {
        unsigned a[2][4];
        #pragma unroll
        for (int mi = 0; mi < 2; mi++) {
            const __half* ap = Ah + (wm * 32 + mi * 16 + g) * 136 + k0 + 2 * t;
            a[mi][0] = *(const unsigned*)(ap);
            a[mi][1] = *(const unsigned*)(ap + 8 * 136);
            a[mi][2] = *(const unsigned*)(ap + 8);
            a[mi][3] = *(const unsigned*)(ap + 8 * 136 + 8);
        }
        unsigned b[4][2];
        #pragma unroll
        for (int ni = 0; ni < 4; ni++) {
            const __half* bp = Wth + (wn * 32 + ni * 8 + g) * 136 + k0 + 2 * t;
            b[ni][0] = *(const unsigned*)(bp);
            b[ni][1] = *(const unsigned*)(bp + 8);
        }
        #pragma unroll
        for (int mi = 0; mi < 2; mi++)
            #pragma unroll
            for (int ni = 0; ni < 4; ni++)
                mma_f16(c[mi][ni], a[mi], b[ni][0], b[ni][1]);
    }
    // stage C (fp32) into smem [64][132]
    __syncthreads();
    float* Sh = (float*)smraw;
    #pragma unroll
    for (int mi = 0; mi < 2; mi++)
        #pragma unroll
        for (int ni = 0; ni < 4; ni++) {
            int r = wm * 32 + mi * 16 + g;
            int col = wn * 32 + ni * 8 + 2 * t;
            Sh[r * 132 + col]           = c[mi][ni][0];
            Sh[r * 132 + col + 1]       = c[mi][ni][1];
            Sh[(r + 8) * 132 + col]     = c[mi][ni][2];
            Sh[(r + 8) * 132 + col + 1] = c[mi][ni][3];
        }
    __syncthreads();
    // fp16 h1 write
    #pragma unroll
    for (int p = 0; p < 8; p++) {
        int task = tid + p * 256;       // 2048 tasks: 64 rows x 32 col-groups(4)
        int row = task >> 5;
        int c4 = (task & 31) * 4;
        int grow = brow + row;
        if (grow < NN) {
            float4 f = *(const float4*)&Sh[row * 132 + c4];
            __half2 h0 = __floats2half2_rn(f.x, f.y);
            __half2 h1 = __floats2half2_rn(f.z, f.w);
            uint2 u = make_uint2(*(unsigned*)&h0, *(unsigned*)&h1);
            *(uint2*)(g_h1h + (size_t)grow * 64 + (task & 31) * 2) = u;
        }
    }
    // attention logits + gmax
    int h = lane >> 3;
    int off = (lane & 7) * 4;
    float4 a4 = *(const float4*)(asrc + h * HID + off);
    float4 d4 = *(const float4*)(adst + h * HID + off);
    #pragma unroll
    for (int rr = 0; rr < 8; rr++) {
        int row = wid * 8 + rr;
        int grow = brow + row;
        float4 hv = *(const float4*)&Sh[row * 132 + lane * 4];
        float ps = hv.x * a4.x + hv.y * a4.y + hv.z * a4.z + hv.w * a4.w;
        float pd = hv.x * d4.x + hv.y * d4.y + hv.z * d4.z + hv.w * d4.w;
        #pragma unroll
        for (int o = 4; o >= 1; o >>= 1) {
            ps += __shfl_xor_sync(0xffffffffu, ps, o);
            pd += __shfl_xor_sync(0xffffffffu, pd, o);
        }
        if ((lane & 7) == 0 && grow < NN) {
            g_esrc1[grow * 4 + h] = ps;
            g_edst1[grow * 4 + h] = pd;
            atomicMaxFShared(&smax[h], ps);
        }
    }
    __syncthreads();
    if (tid < 4) atomicMaxF(&g_gmax1[tid], __int_as_float(smax[tid]));
}

// ---------------- GAT layer 1: shifted softmax + fp16 gather (int4 csrc, x4 MLP) ----------------
__global__ void gat1_kernel(const float* __restrict__ bias) {
    int warp = (blockIdx.x * blockDim.x + threadIdx.x) >> 5;
    int lane = threadIdx.x & 31;
    if (warp >= NN) return;
    int d = warp;
    int base = g_rowptr[d];
    int end  = g_rowptr[d + 1];
    int h = lane >> 3;
    float ed_h = g_edst1[d * 4 + h];
    float S = lrelu(g_gmax1[h] + ed_h);   // upper bound of alpha over neighborhood

    float sum = 0.f;
    float4 acc = make_float4(0.f, 0.f, 0.f, 0.f);
    int j = base;
    int lim = min(end, (base + 3) & ~3);
    for (; j < lim; j++) {
        int s0 = g_csrc[j];
        float w0 = __expf(lrelu(g_esrc1[s0 * 4 + h] + ed_h) - S);
        sum += w0;
        uint2 r0 = *(const uint2*)(g_h1h + (size_t)s0 * 64 + lane * 2);
        float2 p;
        p = __half22float2(*(__half2*)&r0.x); acc.x += w0 * p.x; acc.y += w0 * p.y;
        p = __half22float2(*(__half2*)&r0.y); acc.z += w0 * p.x; acc.w += w0 * p.y;
    }
    for (; j + 3 < end; j += 4) {
        int4 s4 = *(const int4*)(g_csrc + j);
        float w0 = __expf(lrelu(g_esrc1[s4.x * 4 + h] + ed_h) - S);
        float w1 = __expf(lrelu(g_esrc1[s4.y * 4 + h] + ed_h) - S);
        float w2 = __expf(lrelu(g_esrc1[s4.z * 4 + h] + ed_h) - S);
        float w3 = __expf(lrelu(g_esrc1[s4.w * 4 + h] + ed_h) - S);
        uint2 r0 = *(const uint2*)(g_h1h + (size_t)s4.x * 64 + lane * 2);
        uint2 r1 = *(const uint2*)(g_h1h + (size_t)s4.y * 64 + lane * 2);
        uint2 r2 = *(const uint2*)(g_h1h + (size_t)s4.z * 64 + lane * 2);
        uint2 r3 = *(const uint2*)(g_h1h + (size_t)s4.w * 64 + lane * 2);
        sum += (w0 + w1) + (w2 + w3);
        float2 p;
        p = __half22float2(*(__half2*)&r0.x); acc.x += w0 * p.x; acc.y += w0 * p.y;
        p = __half22float2(*(__half2*)&r0.y); acc.z += w0 * p.x; acc.w += w0 * p.y;
        p = __half22float2(*(__half2*)&r1.x); acc.x += w1 * p.x; acc.y += w1 * p.y;
        p = __half22float2(*(__half2*)&r1.y); acc.z += w1 * p.x; acc.w += w1 * p.y;
        p = __half22float2(*(__half2*)&r2.x); acc.x += w2 * p.x; acc.y += w2 * p.y;
        p = __half22float2(*(__half2*)&r2.y); acc.z += w2 * p.x; acc.w += w2 * p.y;
        p = __half22float2(*(__half2*)&r3.x); acc.x += w3 * p.x; acc.y += w3 * p.y;
        p = __half22float2(*(__half2*)&r3.y); acc.z += w3 * p.x; acc.w += w3 * p.y;
    }
    for (; j < end; j++) {
        int s0 = g_csrc[j];
        float w0 = __expf(lrelu(g_esrc1[s0 * 4 + h] + ed_h) - S);
        sum += w0;
        uint2 r0 = *(const uint2*)(g_h1h + (size_t)s0 * 64 + lane * 2);
        float2 p;
        p = __half22float2(*(__half2*)&r0.x); acc.x += w0 * p.x; acc.y += w0 * p.y;
        p = __half22float2(*(__half2*)&r0.y); acc.z += w0 * p.x; acc.w += w0 * p.y;
    }
    float inv = 1.0f / (sum + 1e-16f);
    float4 b = *(const float4*)(bias + lane * 4);
    float4 v;
    v.x = acc.x * inv + b.x;
    v.y = acc.y * inv + b.y;
    v.z = acc.z * inv + b.z;
    v.w = acc.w * inv + b.w;
    v.x = v.x > 0.f ? v.x : (__expf(v.x) - 1.f);
    v.y = v.y > 0.f ? v.y : (__expf(v.y) - 1.f);
    v.z = v.z > 0.f ? v.z : (__expf(v.z) - 1.f);
    v.w = v.w > 0.f ? v.w : (__expf(v.w) - 1.f);
    // store fp16 directly (GEMM2 consumes fp16)
    __half2 o0 = __floats2half2_rn(v.x, v.y);
    __half2 o1 = __floats2half2_rn(v.z, v.w);
    *(uint2*)(g_agg1h + (size_t)d * D1 + lane * 4) = make_uint2(*(unsigned*)&o0, *(unsigned*)&o1);
}

// ---------------- GEMM2 (fp16 mma m16n8k16) + logits + gmax ----------------
// dyn smem: Ah[128][136] + Wth[40][136] halves = 45696 B
#define G2_SMEM ((128 * 136 + 40 * 136) * 2)
__global__ void __launch_bounds__(256, 3) gemm2_kernel(
        const float* __restrict__ asrc, const float* __restrict__ adst) {
    extern __shared__ __half sm2h[];
    __half* Ah  = sm2h;                // [128][136]
    __half* Wth = sm2h + 128 * 136;    // [40 n][136 k]
    __shared__ int smax2;
    int tid = threadIdx.x;
    int brow = blockIdx.x * 128;
    if (tid == 0) smax2 = 0xFF800000;
    // stage A tile (already fp16): pure uint4 copies, 8 per thread
    #pragma unroll
    for (int p = 0; p < 8; p++) {
        int idx = tid + p * 256;        // 2048 uint4 = 128 rows x 16 groups
        int m = idx >> 4;
        int h8 = (idx & 15) * 8;
        int gr = brow + m;
        uint4 v = (gr < NN) ? *(const uint4*)(g_agg1h + (size_t)gr * D1 + h8)
                            : make_uint4(0u, 0u, 0u, 0u);
        *(uint4*)(Ah + m * 136 + h8) = v;
    }
    // stage W2 from pre-transposed fp16: 640 uint4 copies
    #pragma unroll
    for (int p = 0; p < 3; p++) {
        int idx = tid + p * 256;
        if (idx < 640) {
            int n = idx >> 4;
            int gq = (idx & 15) * 8;
            *(uint4*)(Wth + n * 136 + gq) = *(const uint4*)(g_w2t + n * 128 + gq);
        }
    }
    __syncthreads();
    int wid = tid >> 5, lane = tid & 31;
    int g = lane >> 2, t = lane & 3;
    float c[5][4];
    #pragma unroll
    for (int ni = 0; ni < 5; ni++)
        #pragma unroll
        for (int q = 0; q < 4; q++) c[ni][q] = 0.f;
    #pragma unroll
    for (int k0 = 0; k0 < 128; k0 += 16) {
        unsigned a[4];
        const __half* ap = Ah + (wid * 16 + g) * 136 + k0 + 2 * t;
        a[0] = *(const unsigned*)(ap);
        a[1] = *(const unsigned*)(ap + 8 * 136);
        a[2] = *(const unsigned*)(ap + 8);
        a[3] = *(const unsigned*)(ap + 8 * 136 + 8);
        #pragma unroll
        for (int ni = 0; ni < 5; ni++) {
            const __half* bp = Wth + (ni * 8 + g) * 136 + k0 + 2 * t;
            mma_f16(c[ni], a, *(const unsigned*)(bp), *(const unsigned*)(bp + 8));
        }
    }
    // stage C into smem [128][44]
    __syncthreads();
    float* Sh = (float*)sm2h;
    #pragma unroll
    for (int ni = 0; ni < 5; ni++) {
        int r = wid * 16 + g;
        int col = ni * 8 + 2 * t;
        Sh[r * 44 + col]           = c[ni][0];
        Sh[r * 44 + col + 1]       = c[ni][1];
        Sh[(r + 8) * 44 + col]     = c[ni][2];
        Sh[(r + 8) * 44 + col + 1] = c[ni][3];
    }
    __syncthreads();
    // fp16 h2 write: 2 threads per row, 20 cols each
    {
        int row = tid >> 1;
        int half = tid & 1;
        int grow = brow + row;
        if (grow < NN) {
            const float* sp = &Sh[row * 44 + half * 20];
            uint2* op = (uint2*)(g_h2h + (size_t)grow * NC + half * 20);
            #pragma unroll
            for (int i = 0; i < 5; i++) {
                __half2 h0 = __floats2half2_rn(sp[4 * i],     sp[4 * i + 1]);
                __half2 h1 = __floats2half2_rn(sp[4 * i + 2], sp[4 * i + 3]);
                op[i] = make_uint2(*(unsigned*)&h0, *(unsigned*)&h1);
            }
        }
    }
    // attention logits + gmax: each warp handles 16 rows
    float a_lo = __ldg(asrc + lane);
    float d_lo = __ldg(adst + lane);
    float a_hi = (lane < 8) ? __ldg(asrc + 32 + lane) : 0.f;
    float d_hi = (lane < 8) ? __ldg(adst + 32 + lane) : 0.f;
    #pragma unroll
    for (int rr = 0; rr < 16; rr++) {
        int row = wid * 16 + rr;
        int grow = brow + row;
        float v0 = Sh[row * 44 + lane];
        float v1 = (lane < 8) ? Sh[row * 44 + 32 + lane] : 0.f;
        float ps = v0 * a_lo + v1 * a_hi;
        float pd = v0 * d_lo + v1 * d_hi;
        #pragma unroll
        for (int o = 16; o >= 1; o >>= 1) {
            ps += __shfl_xor_sync(0xffffffffu, ps, o);
            pd += __shfl_xor_sync(0xffffffffu, pd, o);
        }
        if (lane == 0 && grow < NN) {
            g_esrc2[grow] = ps;
            g_edst2[grow] = pd;
            atomicMaxFShared(&smax2, ps);
        }
    }
    __syncthreads();
    if (tid == 0) atomicMaxF(&g_gmax2, __int_as_float(smax2));
}

// ---------------- GAT layer 2: shifted softmax + half2 gather (int4 csrc, x4) + log_softmax/softmax ----------------
__global__ void gat2_kernel(const float* __restrict__ bias, float* __restrict__ out) {
    int warp = (blockIdx.x * blockDim.x + threadIdx.x) >> 5;
    int lane = threadIdx.x & 31;
    if (blockIdx.x == 0) {
        if (threadIdx.x < 4) g_gmax1[threadIdx.x] = -1e30f;          // reset for next invocation
        else if (threadIdx.x < 7) g_bar[threadIdx.x - 4] = 0;         // reset grid barriers
    }
    if (warp >= NN) return;
    int d = warp;
    if (lane == 0) g_cnt[d] = 0;   // reset histogram for next invocation
    int base = g_rowptr[d];
    int end  = g_rowptr[d + 1];
    float ed = g_edst2[d];
    float S = lrelu(g_gmax2 + ed);
    bool act = (lane < 20);        // lanes 0..19 own feature pairs (2l, 2l+1)

    float sum = 0.f;
    float2 acc = make_float2(0.f, 0.f);
    int j = base;
    int lim = min(end, (base + 3) & ~3);
    for (; j < lim; j++) {
        int s0 = g_csrc[j];
        float w0 = __expf(lrelu(g_esrc2[s0] + ed) - S);
        sum += w0;
        if (act) {
            unsigned u0 = *(const unsigned*)(g_h2h + (size_t)s0 * NC + 2 * lane);
            float2 p0 = __half22float2(*(__half2*)&u0);
            acc.x += w0 * p0.x; acc.y += w0 * p0.y;
        }
    }
    for (; j + 3 < end; j += 4) {
        int4 s4 = *(const int4*)(g_csrc + j);
        float w0 = __expf(lrelu(g_esrc2[s4.x] + ed) - S);
        float w1 = __expf(lrelu(g_esrc2[s4.y] + ed) - S);
        float w2 = __expf(lrelu(g_esrc2[s4.z] + ed) - S);
        float w3 = __expf(lrelu(g_esrc2[s4.w] + ed) - S);
        sum += (w0 + w1) + (w2 + w3);
        if (act) {
            unsigned u0 = *(const unsigned*)(g_h2h + (size_t)s4.x * NC + 2 * lane);
            unsigned u1 = *(const unsigned*)(g_h2h + (size_t)s4.y * NC + 2 * lane);
            unsigned u2 = *(const unsigned*)(g_h2h + (size_t)s4.z * NC + 2 * lane);
            unsigned u3 = *(const unsigned*)(g_h2h + (size_t)s4.w * NC + 2 * lane);
            float2 p0 = __half22float2(*(__half2*)&u0);
            float2 p1 = __half22float2(*(__half2*)&u1);
            float2 p2 = __half22float2(*(__half2*)&u2);
            float2 p3 = __half22float2(*(__half2*)&u3);
            acc.x += w0 * p0.x + w1 * p1.x;
            acc.y += w0 * p0.y + w1 * p1.y;
            acc.x += w2 * p2.x + w3 * p3.x;
            acc.y += w2 * p2.y + w3 * p3.y;
        }
    }
    for (; j < end; j++) {
        int s0 = g_csrc[j];
        float w0 = __expf(lrelu(g_esrc2[s0] + ed) - S);
        sum += w0;
        if (act) {
            unsigned u0 = *(const unsigned*)(g_h2h + (size_t)s0 * NC + 2 * lane);
            float2 p0 = __half22float2(*(__half2*)&u0);
            acc.x += w0 * p0.x; acc.y += w0 * p0.y;
        }
    }
    float inv = 1.0f / (sum + 1e-16f);
    float2 bb = act ? __ldg((const float2*)bias + lane) : make_float2(0.f, 0.f);
    float v0 = acc.x * inv + bb.x;   // class 2*lane
    float v1 = acc.y * inv + bb.y;   // class 2*lane+1
    float m = act ? fmaxf(v0, v1) : -INFINITY;
    #pragma unroll
    for (int o = 16; o >= 1; o >>= 1) m = fmaxf(m, __shfl_xor_sync(0xffffffffu, m, o));
    float e0 = act ? expf(v0 - m) : 0.f;
    float e1 = act ? expf(v1 - m) : 0.f;
    float sm = e0 + e1;
    #pragma unroll
    for (int o = 16; o >= 1; o >>= 1) sm += __shfl_xor_sync(0xffffffffu, sm, o);
    float ls = logf(sm);
    float invs = 1.0f / sm;
    if (act) {
        float* lo = out + (size_t)d * NC + 2 * lane;
        float* so = out + (size_t)NN * NC + (size_t)d * NC + 2 * lane;
        *(float2*)lo = make_float2(v0 - m - ls, v1 - m - ls);
        *(float2*)so = make_float2(e0 * invs, e1 * invs);
    }
}

// ---------------- launch ----------------
extern "C" void kernel_launch(void* const* d_in, const int* in_sizes, int n_in,
                              void* d_out, int out_size) {
    const float* x   = (const float*)d_in[0];
    const int*   ei  = (const int*)d_in[1];
    const float* W1  = (const float*)d_in[2];
    const float* as1 = (const float*)d_in[3];
    const float* ad1 = (const float*)d_in[4];
    const float* b1  = (const float*)d_in[5];
    const float* W2  = (const float*)d_in[6];
    const float* as2 = (const float*)d_in[7];
    const float* ad2 = (const float*)d_in[8];
    const float* b2  = (const float*)d_in[9];
    float* out = (float*)d_out;
    const int* src = ei;
    const int* dst = ei + NE;

    cudaFuncSetAttribute(fused1_kernel, cudaFuncAttributeMaxDynamicSharedMemorySize, G1_SMEM);
    cudaFuncSetAttribute(gemm2_kernel, cudaFuncAttributeMaxDynamicSharedMemorySize, G2_SMEM);

    prep_kernel<<<84, 256>>>(W1, W2);
    fused1_kernel<<<CSRB + G1B, 256, G1_SMEM>>>(src, dst, x, as1, ad1);
    gat1_kernel<<<6250, 256>>>(b1);
    gemm2_kernel<<<391, 256, G2_SMEM>>>(as2, ad2);
    gat2_kernel<<<6250, 256>>>(b2, out);
}